// round 10
// baseline (speedup 1.0000x reference)
#include <cuda_runtime.h>
#include <cuda_fp16.h>
#include <cstdint>

// InstantNGP 2D hash-grid bilinear lookup — two-pass de-hash, fp16 records,
// grid-stride persistent lookup with coordinate prefetch.
//
// Pass 1 (dehash): pack all 4 corner features of each cell as 8 fp16 into one
// 16-byte record (coalesced gathers: hash permutes c0 within aligned blocks).
// Pass 2 (lookup): single wave of CTAs, grid-stride over point-pairs; each
// iteration prefetches the NEXT pair's coords while the current pair's two
// scattered LDG.128 gathers + bilinear are in flight. Removes the serial
// x-load -> gather chain and all wave-transition overhead.

#define TABLE_MASK 524287u
#define PI2 2654435761u
#define GRID 1024

// 1024*1024 cells * 16B = 16.8 MB scratch.
__device__ uint4 g_H[GRID * GRID];

__device__ __forceinline__ unsigned hashidx(unsigned c0, unsigned c1) {
    return (c0 ^ (c1 * PI2)) & TABLE_MASK;
}

__global__ __launch_bounds__(256)
void dehash_kernel(const float2* __restrict__ table)
{
    int i = blockIdx.x * blockDim.x + threadIdx.x;   // cell id
    unsigned c0 = (unsigned)(i & (GRID - 1));
    unsigned c1 = (unsigned)(i >> 10);

    float2 f00 = __ldg(&table[hashidx(c0,      c1)]);
    float2 f10 = __ldg(&table[hashidx(c0 + 1u, c1)]);
    float2 f01 = __ldg(&table[hashidx(c0,      c1 + 1u)]);
    float2 f11 = __ldg(&table[hashidx(c0 + 1u, c1 + 1u)]);

    half2 h00 = __float22half2_rn(f00);
    half2 h10 = __float22half2_rn(f10);
    half2 h01 = __float22half2_rn(f01);
    half2 h11 = __float22half2_rn(f11);

    uint4 rec;
    rec.x = *reinterpret_cast<unsigned*>(&h00);
    rec.y = *reinterpret_cast<unsigned*>(&h10);
    rec.z = *reinterpret_cast<unsigned*>(&h01);
    rec.w = *reinterpret_cast<unsigned*>(&h11);
    g_H[i] = rec;
}

__device__ __forceinline__ void process_pair(
    float4 p, float4* __restrict__ out4, int i)
{
    float px[2] = {p.x, p.z};
    float py[2] = {p.y, p.w};

    float fx[2], fy[2];
    unsigned cell[2];

    #pragma unroll
    for (int j = 0; j < 2; j++) {
        float xs = px[j] * 1024.0f;
        float ys = py[j] * 1024.0f;
        float fx0 = floorf(xs);
        float fy0 = floorf(ys);
        fx[j] = xs - fx0;
        fy[j] = ys - fy0;
        cell[j] = (((unsigned)fy0) << 10) | (unsigned)fx0;
    }

    uint4 rec[2];
    rec[0] = __ldg(&g_H[cell[0]]);
    rec[1] = __ldg(&g_H[cell[1]]);

    float o[4];
    #pragma unroll
    for (int j = 0; j < 2; j++) {
        float2 f00 = __half22float2(*reinterpret_cast<half2*>(&rec[j].x));
        float2 f10 = __half22float2(*reinterpret_cast<half2*>(&rec[j].y));
        float2 f01 = __half22float2(*reinterpret_cast<half2*>(&rec[j].z));
        float2 f11 = __half22float2(*reinterpret_cast<half2*>(&rec[j].w));

        float gx = 1.0f - fx[j];
        float gy = 1.0f - fy[j];
        float w00 = gx * gy;
        float w10 = fx[j] * gy;
        float w01 = gx * fy[j];
        float w11 = fx[j] * fy[j];

        o[2 * j + 0] = f00.x * w00 + f10.x * w10 + f01.x * w01 + f11.x * w11;
        o[2 * j + 1] = f00.y * w00 + f10.y * w10 + f01.y * w01 + f11.y * w11;
    }

    out4[i] = make_float4(o[0], o[1], o[2], o[3]);
}

__global__ __launch_bounds__(128)
void lookup_kernel(const float4* __restrict__ x4,
                   float4* __restrict__ out4,
                   int npack)   // npack = n/2 (2 points per thread-iteration)
{
    int stride = gridDim.x * blockDim.x;
    int i = blockIdx.x * blockDim.x + threadIdx.x;
    if (i >= npack) return;

    float4 p = __ldg(&x4[i]);          // prime the pipeline

    int inext = i + stride;
    while (inext < npack) {
        float4 pn = __ldg(&x4[inext]); // prefetch next coords (independent)
        process_pair(p, out4, i);      // gathers + compute + store for current
        p = pn;
        i = inext;
        inext += stride;
    }
    process_pair(p, out4, i);          // epilogue
}

extern "C" void kernel_launch(void* const* d_in, const int* in_sizes, int n_in,
                              void* d_out, int out_size)
{
    const float4* x4    = (const float4*)d_in[0];   // [B,2] f32 as float4
    const float2* table = (const float2*)d_in[1];   // [524288,2] f32
    float4* out4        = (float4*)d_out;

    int n = in_sizes[0] / 2;   // number of points (4194304, divisible by 2)
    int npack = n / 2;

    int cells = GRID * GRID;
    dehash_kernel<<<cells / 256, 256>>>(table);

    // Single wave: 148 SMs x 16 resident CTAs (128 thr, ~36 regs) = 2368 CTAs.
    int blocks = 148 * 16;
    lookup_kernel<<<blocks, 128>>>(x4, out4, npack);
}

// round 11
// speedup vs baseline: 1.0681x; 1.0681x over previous
#include <cuda_runtime.h>
#include <cuda_fp16.h>
#include <cstdint>

// InstantNGP 2D hash-grid bilinear lookup — two-pass de-hash, fp16 records.
//
// Pass 1 (dehash): pack all 4 corner features of each cell as 8 fp16 into one
// 16-byte record (coalesced gathers: hash permutes c0 within aligned blocks).
// Pass 2 (lookup, R9 shape): 2 points/thread, 128-thread blocks, 16384 CTAs.
// R11: streaming cache hints — x via __ldcs, out via __stcs — so the 64MB
// one-touch coord/out streams don't evict the 16.8MB H table from L2;
// gathers then hit L2 (~234cyc) instead of falling to DRAM (~577cyc).

#define TABLE_MASK 524287u
#define PI2 2654435761u
#define GRID 1024

// 1024*1024 cells * 16B = 16.8 MB scratch.
__device__ uint4 g_H[GRID * GRID];

__device__ __forceinline__ unsigned hashidx(unsigned c0, unsigned c1) {
    return (c0 ^ (c1 * PI2)) & TABLE_MASK;
}

__global__ __launch_bounds__(256)
void dehash_kernel(const float2* __restrict__ table)
{
    int i = blockIdx.x * blockDim.x + threadIdx.x;   // cell id
    unsigned c0 = (unsigned)(i & (GRID - 1));
    unsigned c1 = (unsigned)(i >> 10);

    float2 f00 = __ldg(&table[hashidx(c0,      c1)]);
    float2 f10 = __ldg(&table[hashidx(c0 + 1u, c1)]);
    float2 f01 = __ldg(&table[hashidx(c0,      c1 + 1u)]);
    float2 f11 = __ldg(&table[hashidx(c0 + 1u, c1 + 1u)]);

    half2 h00 = __float22half2_rn(f00);
    half2 h10 = __float22half2_rn(f10);
    half2 h01 = __float22half2_rn(f01);
    half2 h11 = __float22half2_rn(f11);

    uint4 rec;
    rec.x = *reinterpret_cast<unsigned*>(&h00);
    rec.y = *reinterpret_cast<unsigned*>(&h10);
    rec.z = *reinterpret_cast<unsigned*>(&h01);
    rec.w = *reinterpret_cast<unsigned*>(&h11);
    g_H[i] = rec;
}

__global__ __launch_bounds__(128)
void lookup_kernel(const float4* __restrict__ x4,
                   float4* __restrict__ out4,
                   int npack)   // npack = n/2 (2 points per thread)
{
    int i = blockIdx.x * blockDim.x + threadIdx.x;
    if (i >= npack) return;

    float4 p = __ldcs(&x4[i]);   // streaming read: don't pollute L2
    float px[2] = {p.x, p.z};
    float py[2] = {p.y, p.w};

    float fx[2], fy[2];
    unsigned cell[2];

    #pragma unroll
    for (int j = 0; j < 2; j++) {
        float xs = px[j] * 1024.0f;
        float ys = py[j] * 1024.0f;
        float fx0 = floorf(xs);
        float fy0 = floorf(ys);
        fx[j] = xs - fx0;
        fy[j] = ys - fy0;
        cell[j] = (((unsigned)fy0) << 10) | (unsigned)fx0;
    }

    // 2 independent scattered LDG.128 (default caching: H should stay L2-hot).
    uint4 rec[2];
    rec[0] = __ldg(&g_H[cell[0]]);
    rec[1] = __ldg(&g_H[cell[1]]);

    float o[4];
    #pragma unroll
    for (int j = 0; j < 2; j++) {
        float2 f00 = __half22float2(*reinterpret_cast<half2*>(&rec[j].x));
        float2 f10 = __half22float2(*reinterpret_cast<half2*>(&rec[j].y));
        float2 f01 = __half22float2(*reinterpret_cast<half2*>(&rec[j].z));
        float2 f11 = __half22float2(*reinterpret_cast<half2*>(&rec[j].w));

        float gx = 1.0f - fx[j];
        float gy = 1.0f - fy[j];
        float w00 = gx * gy;
        float w10 = fx[j] * gy;
        float w01 = gx * fy[j];
        float w11 = fx[j] * fy[j];

        o[2 * j + 0] = f00.x * w00 + f10.x * w10 + f01.x * w01 + f11.x * w11;
        o[2 * j + 1] = f00.y * w00 + f10.y * w10 + f01.y * w01 + f11.y * w11;
    }

    __stcs(&out4[i], make_float4(o[0], o[1], o[2], o[3]));  // streaming write
}

extern "C" void kernel_launch(void* const* d_in, const int* in_sizes, int n_in,
                              void* d_out, int out_size)
{
    const float4* x4    = (const float4*)d_in[0];   // [B,2] f32 as float4
    const float2* table = (const float2*)d_in[1];   // [524288,2] f32
    float4* out4        = (float4*)d_out;

    int n = in_sizes[0] / 2;   // number of points (4194304, divisible by 2)
    int npack = n / 2;

    int cells = GRID * GRID;
    dehash_kernel<<<cells / 256, 256>>>(table);
    lookup_kernel<<<(npack + 127) / 128, 128>>>(x4, out4, npack);
}